// round 8
// baseline (speedup 1.0000x reference)
#include <cuda_runtime.h>

#define NN     50000
#define EE     800000
#define NHD    4
#define NC     32
#define HC     128
#define NL     3
#define OUTC   10
#define CAP    96
#define BN_EPS 1e-5f

// ---------------- static device scratch ----------------
__device__ __align__(16) float g_buf0[NN * HC];
__device__ __align__(16) float g_buf1[NN * HC];
__device__ __align__(16) float g_y[NN * NC];
__device__ __align__(16) float g_as[NN * NHD];
__device__ __align__(16) float g_ad[NN * NHD];
__device__ float g_sumL[NL][HC];
__device__ float g_sqL[NL][HC];
__device__ __align__(16) float g_linP[NC * HC];
__device__ float g_const[NC];
__device__ float g_attF[2][HC];
__device__ int   g_deg[NN];
__device__ int   g_pad[NN * CAP];

__device__ __forceinline__ float* bufPtr(int b) { return b ? g_buf1 : g_buf0; }

__device__ __forceinline__ float lrelu_exp(float z) {
    z = (z > 0.f) ? z : 0.2f * z;
    return __expf(z);
}

// ---------------- kernels ----------------

__global__ void k_init(float* __restrict__ out, int out_n, int N) {
    int gid = blockIdx.x * blockDim.x + threadIdx.x;
    if (gid < N) g_deg[gid] = 0;
    if (gid < NL * HC) { (&g_sumL[0][0])[gid] = 0.f; (&g_sqL[0][0])[gid] = 0.f; }
    if (gid < out_n) out[gid] = 0.f;
}

// Block-range fused: [0,nA): embed gather + layer-0 BN stats.  [nA,...): padded-CSR scatter.
__global__ void __launch_bounds__(256)
k_embed_scatter(const int* __restrict__ xidx, const float* __restrict__ embed,
                const int* __restrict__ ei, int N, int E, int nA) {
    int tid = threadIdx.x;
    if ((int)blockIdx.x < nA) {
        __shared__ float sS[2][HC], sQ[2][HC];
        int c = tid & 127, sub = tid >> 7;
        int r0 = blockIdx.x * 64;
        float s = 0.f, s2 = 0.f;
#pragma unroll 4
        for (int it = 0; it < 32; it++) {
            int r = r0 + sub + it * 2;
            if (r < N) {
                float v = embed[xidx[r] * HC + c];
                g_buf0[r * HC + c] = v;
                s += v; s2 += v * v;
            }
        }
        sS[sub][c] = s; sQ[sub][c] = s2;
        __syncthreads();
        if (tid < HC) {
            atomicAdd(&g_sumL[0][tid], sS[0][tid] + sS[1][tid]);
            atomicAdd(&g_sqL[0][tid], sQ[0][tid] + sQ[1][tid]);
        }
    } else {
        int gid = (blockIdx.x - nA) * 256 + tid;
        if (gid < E) {
            int s = ei[gid], d = ei[E + gid];
            int pos = atomicAdd(&g_deg[d], 1);
            g_pad[d * CAP + pos] = s;
        }
    }
}

// Per-layer weight folding (one block).
__global__ void __launch_bounds__(128)
k_prep(int l,
       const float* __restrict__ linW, const float* __restrict__ linb,
       const float* __restrict__ gatW,
       const float* __restrict__ attS, const float* __restrict__ attD,
       const float* __restrict__ bng, const float* __restrict__ bnb, int N) {
    __shared__ float sScale[HC], sShift[HC];
    int tid = threadIdx.x;
    {
        float invN = 1.0f / (float)N;
        float mean = g_sumL[l][tid] * invN;
        float var  = g_sqL[l][tid] * invN - mean * mean;
        float rstd = rsqrtf(var + BN_EPS);
        float sc = bng[l * HC + tid] * rstd;
        sScale[tid] = sc;
        sShift[tid] = bnb[l * HC + tid] - sc * mean;
    }
    __syncthreads();
#pragma unroll
    for (int j = 0; j < 32; j++) {
        int i = tid + j * 128;
        int k = i & 127;
        g_linP[i] = linW[l * NC * HC + i] * sScale[k];
    }
    if (tid < NC) {
        float cst = linb[l * NC + tid];
        const float* lw = &linW[l * NC * HC + tid * HC];
        for (int k = 0; k < HC; k++) cst = fmaf(lw[k], sShift[k], cst);
        g_const[tid] = cst;
    }
    {
        int hd = tid >> 5, cc = tid & 31;
        float a = 0.f, b = 0.f;
        for (int j = 0; j < 32; j++) {
            int r = hd * 32 + j;
            float w = __ldg(&gatW[l * HC * NC + r * NC + cc]);
            a = fmaf(w, __ldg(&attS[l * HC + r]), a);
            b = fmaf(w, __ldg(&attD[l * HC + r]), b);
        }
        g_attF[0][tid] = a;
        g_attF[1][tid] = b;
    }
}

// Per-node GEMM: 64 nodes/block, 4 threads per node (8 output channels each).
__global__ void __launch_bounds__(256)
k_node(int inB, int N) {
    __shared__ __align__(16) float sLinP[NC * HC];     // [c][k]
    __shared__ __align__(16) float sX[64 * 33];        // tile / y staging
    __shared__ float sAs[HC], sAd[HC], sConst[NC];

    int tid = threadIdx.x;
    for (int i = tid; i < NC * HC; i += 256) sLinP[i] = g_linP[i];
    if (tid < HC) { sAs[tid] = g_attF[0][tid]; sAd[tid] = g_attF[1][tid]; }
    if (tid < NC) sConst[tid] = g_const[tid];
    __syncthreads();   // <<< R7 bug fix: sConst/sAs/sAd must be visible before use

    int n0 = blockIdx.x * 64;
    int nd = tid >> 2, p = tid & 3;
    int n = n0 + nd;
    const float* __restrict__ xb = bufPtr(inB);

    float y8[8];
#pragma unroll
    for (int cc = 0; cc < 8; cc++) y8[cc] = sConst[p * 8 + cc];

#pragma unroll
    for (int kt = 0; kt < 4; kt++) {
        __syncthreads();
#pragma unroll
        for (int j = 0; j < 8; j++) {
            int i = tid + j * 256;
            int ni = i >> 5, ki = i & 31;
            int nn = n0 + ni;
            sX[ni * 33 + ki] = (nn < N) ? xb[nn * HC + kt * 32 + ki] : 0.f;
        }
        __syncthreads();
        float xk[32];
        const float* xr = &sX[nd * 33];
#pragma unroll
        for (int kk = 0; kk < 32; kk++) xk[kk] = xr[kk];
#pragma unroll
        for (int cc = 0; cc < 8; cc++) {
            int c = p * 8 + cc;
            const float4* w4 = reinterpret_cast<const float4*>(&sLinP[c * HC + kt * 32]);
            float acc = y8[cc];
#pragma unroll
            for (int q = 0; q < 8; q++) {
                float4 w = w4[q];
                acc = fmaf(xk[4 * q], w.x, acc);
                acc = fmaf(xk[4 * q + 1], w.y, acc);
                acc = fmaf(xk[4 * q + 2], w.z, acc);
                acc = fmaf(xk[4 * q + 3], w.w, acc);
            }
            y8[cc] = acc;
        }
    }
#pragma unroll
    for (int cc = 0; cc < 8; cc++) y8[cc] = fmaxf(y8[cc], 0.f);

    // attention partial dots over this thread's 8 channels, reduce across the 4-thread group
    float asH[4] = {0.f, 0.f, 0.f, 0.f}, adH[4] = {0.f, 0.f, 0.f, 0.f};
#pragma unroll
    for (int cc = 0; cc < 8; cc++) {
        int c = p * 8 + cc;
        float yv = y8[cc];
#pragma unroll
        for (int h = 0; h < 4; h++) {
            asH[h] = fmaf(yv, sAs[h * 32 + c], asH[h]);
            adH[h] = fmaf(yv, sAd[h * 32 + c], adH[h]);
        }
    }
#pragma unroll
    for (int off = 1; off <= 2; off <<= 1) {
#pragma unroll
        for (int h = 0; h < 4; h++) {
            asH[h] += __shfl_xor_sync(0xffffffffu, asH[h], off);
            adH[h] += __shfl_xor_sync(0xffffffffu, adH[h], off);
        }
    }
    if (p == 0 && n < N) {
        *reinterpret_cast<float4*>(&g_as[n * NHD]) = make_float4(asH[0], asH[1], asH[2], asH[3]);
        *reinterpret_cast<float4*>(&g_ad[n * NHD]) = make_float4(adH[0], adH[1], adH[2], adH[3]);
    }

    // stage y into smem, then coalesced global write
    __syncthreads();
#pragma unroll
    for (int cc = 0; cc < 8; cc++) sX[nd * 33 + p * 8 + cc] = y8[cc];
    __syncthreads();
#pragma unroll
    for (int j = 0; j < 8; j++) {
        int i = tid + j * 256;
        int ni = i >> 5, ci = i & 31;
        int nn = n0 + ni;
        if (nn < N) g_y[nn * NC + ci] = sX[ni * 33 + ci];
    }
}

// Gather: 32 nodes/block, 4 per warp; 4 edges consumed in parallel per warp.
__global__ void __launch_bounds__(256)
k_gather(int outB, const float* __restrict__ gatW, const float* __restrict__ gatb,
         const float* __restrict__ rW, const float* __restrict__ rb,
         const int* __restrict__ batch, float* __restrict__ out,
         int l, int N, int mode) {
    __shared__ __align__(16) float sGatW[HC * 33];
    __shared__ __align__(16) float4 sW[8][32];
    __shared__ int sS[8][32];
    __shared__ __align__(16) float sOut[32][132];
    __shared__ float sRW[OUTC * HC];
    __shared__ float sGatB[HC];

    int tid = threadIdx.x;
    int wid = tid >> 5, lane = tid & 31;
    for (int m = tid; m < HC * NC; m += 256) {
        int r = m >> 5, c = m & 31;
        sGatW[r * 33 + c] = gatW[l * HC * NC + m];
    }
    if (tid < HC) sGatB[tid] = gatb[l * HC + tid];
    if (mode == 1)
        for (int m = tid; m < OUTC * HC; m += 256) sRW[m] = rW[m];
    __syncthreads();

    int hd = lane >> 3, q = lane & 7;
    int grp = lane >> 3;
    const float* __restrict__ ybase = g_y;

#pragma unroll 1
    for (int i4 = 0; i4 < 4; i4++) {
        int nl = wid * 4 + i4;
        int gw = blockIdx.x * 32 + nl;
        bool valid = (gw < N);
        int gws = valid ? gw : 0;

        int cnt = valid ? g_deg[gws] : 0;
        const int* __restrict__ lst = &g_pad[gws * CAP];
        float4 ad4 = make_float4(0.f, 0.f, 0.f, 0.f);
        float4 asSelf = make_float4(0.f, 0.f, 0.f, 0.f);
        if (valid) {
            ad4 = *reinterpret_cast<const float4*>(&g_ad[gws * NHD]);
            asSelf = *reinterpret_cast<const float4*>(&g_as[gws * NHD]);
        }
        float4 wself;
        wself.x = lrelu_exp(asSelf.x + ad4.x);
        wself.y = lrelu_exp(asSelf.y + ad4.y);
        wself.z = lrelu_exp(asSelf.z + ad4.z);
        wself.w = lrelu_exp(asSelf.w + ad4.w);

        float4 accH0 = make_float4(0.f, 0.f, 0.f, 0.f);
        float4 accH1 = make_float4(0.f, 0.f, 0.f, 0.f);
        float4 accH2 = make_float4(0.f, 0.f, 0.f, 0.f);
        float4 accH3 = make_float4(0.f, 0.f, 0.f, 0.f);
        float4 wsum4 = make_float4(0.f, 0.f, 0.f, 0.f);

        for (int base = 0; base < cnt; base += 32) {
            int c2 = min(32, cnt - base);
            int s_l = 0;
            float4 w4 = make_float4(0.f, 0.f, 0.f, 0.f);
            if (lane < c2) {
                s_l = lst[base + lane];
                const float4 as4 = *reinterpret_cast<const float4*>(&g_as[s_l * NHD]);
                w4.x = lrelu_exp(as4.x + ad4.x);
                w4.y = lrelu_exp(as4.y + ad4.y);
                w4.z = lrelu_exp(as4.z + ad4.z);
                w4.w = lrelu_exp(as4.w + ad4.w);
            }
            wsum4.x += w4.x; wsum4.y += w4.y; wsum4.z += w4.z; wsum4.w += w4.w;
            sS[wid][lane] = s_l;
            sW[wid][lane] = w4;
            __syncwarp();

            int j = grp;
            for (; j + 4 < c2; j += 8) {
                int sA = sS[wid][j], sB = sS[wid][j + 4];
                float4 weA = sW[wid][j], weB = sW[wid][j + 4];
                const float4 yA = *reinterpret_cast<const float4*>(&ybase[sA * NC + q * 4]);
                const float4 yB = *reinterpret_cast<const float4*>(&ybase[sB * NC + q * 4]);
                accH0.x = fmaf(weA.x, yA.x, accH0.x); accH0.y = fmaf(weA.x, yA.y, accH0.y);
                accH0.z = fmaf(weA.x, yA.z, accH0.z); accH0.w = fmaf(weA.x, yA.w, accH0.w);
                accH1.x = fmaf(weA.y, yA.x, accH1.x); accH1.y = fmaf(weA.y, yA.y, accH1.y);
                accH1.z = fmaf(weA.y, yA.z, accH1.z); accH1.w = fmaf(weA.y, yA.w, accH1.w);
                accH2.x = fmaf(weA.z, yA.x, accH2.x); accH2.y = fmaf(weA.z, yA.y, accH2.y);
                accH2.z = fmaf(weA.z, yA.z, accH2.z); accH2.w = fmaf(weA.z, yA.w, accH2.w);
                accH3.x = fmaf(weA.w, yA.x, accH3.x); accH3.y = fmaf(weA.w, yA.y, accH3.y);
                accH3.z = fmaf(weA.w, yA.z, accH3.z); accH3.w = fmaf(weA.w, yA.w, accH3.w);
                accH0.x = fmaf(weB.x, yB.x, accH0.x); accH0.y = fmaf(weB.x, yB.y, accH0.y);
                accH0.z = fmaf(weB.x, yB.z, accH0.z); accH0.w = fmaf(weB.x, yB.w, accH0.w);
                accH1.x = fmaf(weB.y, yB.x, accH1.x); accH1.y = fmaf(weB.y, yB.y, accH1.y);
                accH1.z = fmaf(weB.y, yB.z, accH1.z); accH1.w = fmaf(weB.y, yB.w, accH1.w);
                accH2.x = fmaf(weB.z, yB.x, accH2.x); accH2.y = fmaf(weB.z, yB.y, accH2.y);
                accH2.z = fmaf(weB.z, yB.z, accH2.z); accH2.w = fmaf(weB.z, yB.w, accH2.w);
                accH3.x = fmaf(weB.w, yB.x, accH3.x); accH3.y = fmaf(weB.w, yB.y, accH3.y);
                accH3.z = fmaf(weB.w, yB.z, accH3.z); accH3.w = fmaf(weB.w, yB.w, accH3.w);
            }
            if (j < c2) {
                int sA = sS[wid][j];
                float4 weA = sW[wid][j];
                const float4 yA = *reinterpret_cast<const float4*>(&ybase[sA * NC + q * 4]);
                accH0.x = fmaf(weA.x, yA.x, accH0.x); accH0.y = fmaf(weA.x, yA.y, accH0.y);
                accH0.z = fmaf(weA.x, yA.z, accH0.z); accH0.w = fmaf(weA.x, yA.w, accH0.w);
                accH1.x = fmaf(weA.y, yA.x, accH1.x); accH1.y = fmaf(weA.y, yA.y, accH1.y);
                accH1.z = fmaf(weA.y, yA.z, accH1.z); accH1.w = fmaf(weA.y, yA.w, accH1.w);
                accH2.x = fmaf(weA.z, yA.x, accH2.x); accH2.y = fmaf(weA.z, yA.y, accH2.y);
                accH2.z = fmaf(weA.z, yA.z, accH2.z); accH2.w = fmaf(weA.z, yA.w, accH2.w);
                accH3.x = fmaf(weA.w, yA.x, accH3.x); accH3.y = fmaf(weA.w, yA.y, accH3.y);
                accH3.z = fmaf(weA.w, yA.z, accH3.z); accH3.w = fmaf(weA.w, yA.w, accH3.w);
            }
            __syncwarp();
        }

#pragma unroll
        for (int off = 8; off <= 16; off <<= 1) {
            accH0.x += __shfl_xor_sync(0xffffffffu, accH0.x, off);
            accH0.y += __shfl_xor_sync(0xffffffffu, accH0.y, off);
            accH0.z += __shfl_xor_sync(0xffffffffu, accH0.z, off);
            accH0.w += __shfl_xor_sync(0xffffffffu, accH0.w, off);
            accH1.x += __shfl_xor_sync(0xffffffffu, accH1.x, off);
            accH1.y += __shfl_xor_sync(0xffffffffu, accH1.y, off);
            accH1.z += __shfl_xor_sync(0xffffffffu, accH1.z, off);
            accH1.w += __shfl_xor_sync(0xffffffffu, accH1.w, off);
            accH2.x += __shfl_xor_sync(0xffffffffu, accH2.x, off);
            accH2.y += __shfl_xor_sync(0xffffffffu, accH2.y, off);
            accH2.z += __shfl_xor_sync(0xffffffffu, accH2.z, off);
            accH2.w += __shfl_xor_sync(0xffffffffu, accH2.w, off);
            accH3.x += __shfl_xor_sync(0xffffffffu, accH3.x, off);
            accH3.y += __shfl_xor_sync(0xffffffffu, accH3.y, off);
            accH3.z += __shfl_xor_sync(0xffffffffu, accH3.z, off);
            accH3.w += __shfl_xor_sync(0xffffffffu, accH3.w, off);
        }
        float4 acc = (hd == 0) ? accH0 : (hd == 1) ? accH1 : (hd == 2) ? accH2 : accH3;

#pragma unroll
        for (int off = 16; off; off >>= 1) {
            wsum4.x += __shfl_xor_sync(0xffffffffu, wsum4.x, off);
            wsum4.y += __shfl_xor_sync(0xffffffffu, wsum4.y, off);
            wsum4.z += __shfl_xor_sync(0xffffffffu, wsum4.z, off);
            wsum4.w += __shfl_xor_sync(0xffffffffu, wsum4.w, off);
        }
        wsum4.x += wself.x; wsum4.y += wself.y; wsum4.z += wself.z; wsum4.w += wself.w;
        float wsh = (hd == 0) ? wself.x : (hd == 1) ? wself.y : (hd == 2) ? wself.z : wself.w;
        const float4 ys = *reinterpret_cast<const float4*>(&ybase[gws * NC + q * 4]);
        acc.x = fmaf(wsh, ys.x, acc.x); acc.y = fmaf(wsh, ys.y, acc.y);
        acc.z = fmaf(wsh, ys.z, acc.z); acc.w = fmaf(wsh, ys.w, acc.w);
        float wsumh = (hd == 0) ? wsum4.x : (hd == 1) ? wsum4.y : (hd == 2) ? wsum4.z : wsum4.w;
        float inv = 1.f / (wsumh + 1e-16f);
        acc.x *= inv; acc.y *= inv; acc.z *= inv; acc.w *= inv;

        *reinterpret_cast<float4*>(&sOut[nl][lane * 4]) = acc;
        __syncwarp();

        float a[4];
#pragma unroll
        for (int i = 0; i < 4; i++) {
            int o = lane + 32 * i;
            float v = sGatB[o];
            const float* aggh = &sOut[nl][i * 32];
            const float* wrow = &sGatW[o * 33];
#pragma unroll
            for (int c = 0; c < 32; c++) v = fmaf(wrow[c], aggh[c], v);
            a[i] = valid ? v : 0.f;
        }
        __syncwarp();
#pragma unroll
        for (int i = 0; i < 4; i++) sOut[nl][lane + 32 * i] = a[i];

        if (mode == 0) {
            if (valid) {
                float* outrow = bufPtr(outB) + gw * HC;
#pragma unroll
                for (int i = 0; i < 4; i++) outrow[lane + 32 * i] = a[i];
            }
        } else if (valid) {
            int g = batch[gw];
#pragma unroll
            for (int o = 0; o < OUTC; o++) {
                float pdot = 0.f;
#pragma unroll
                for (int i = 0; i < 4; i++)
                    pdot = fmaf(a[i], sRW[o * HC + lane + 32 * i], pdot);
#pragma unroll
                for (int off = 16; off; off >>= 1)
                    pdot += __shfl_xor_sync(0xffffffffu, pdot, off);
                if (lane == o) atomicAdd(&out[g * OUTC + o], pdot + __ldg(&rb[o]));
            }
        }
    }

    if (mode == 0) {
        __syncthreads();
        if (tid < HC) {
            float s = 0.f, s2 = 0.f;
#pragma unroll
            for (int w = 0; w < 32; w++) {
                float v = sOut[w][tid];
                s += v; s2 += v * v;
            }
            atomicAdd(&g_sumL[l + 1][tid], s);
            atomicAdd(&g_sqL[l + 1][tid], s2);
        }
    }
}

// ---------------- launch ----------------
extern "C" void kernel_launch(void* const* d_in, const int* in_sizes, int n_in,
                              void* d_out, int out_size) {
    const int*   xidx  = (const int*)d_in[0];
    const int*   ei    = (const int*)d_in[1];
    const int*   batch = (const int*)d_in[2];
    const float* embed = (const float*)d_in[3];
    const float* bng   = (const float*)d_in[4];
    const float* bnb   = (const float*)d_in[5];
    const float* linW  = (const float*)d_in[6];
    const float* linb  = (const float*)d_in[7];
    const float* gatW  = (const float*)d_in[8];
    const float* attS  = (const float*)d_in[9];
    const float* attD  = (const float*)d_in[10];
    const float* gatb  = (const float*)d_in[11];
    const float* rW    = (const float*)d_in[12];
    const float* rb    = (const float*)d_in[13];
    float* out = (float*)d_out;

    int N = in_sizes[0];
    int E = in_sizes[1] / 2;
    int nA = (N + 63) / 64;
    int nB = (E + 255) / 256;

    k_init<<<(N + 255) / 256, 256>>>(out, out_size, N);
    k_embed_scatter<<<nA + nB, 256>>>(xidx, embed, ei, N, E, nA);

    for (int l = 0; l < NL; l++) {
        int inB = l & 1;
        int outB = inB ^ 1;
        int mode = (l == NL - 1) ? 1 : 0;
        k_prep<<<1, 128>>>(l, linW, linb, gatW, attS, attD, bng, bnb, N);
        k_node<<<(N + 63) / 64, 256>>>(inB, N);
        k_gather<<<(N + 31) / 32, 256>>>(outB, gatW, gatb, rW, rb, batch, out, l, N, mode);
    }
}

// round 9
// speedup vs baseline: 1.0501x; 1.0501x over previous
#include <cuda_runtime.h>

#define NN     50000
#define EE     800000
#define NHD    4
#define NC     32
#define HC     128
#define NL     3
#define OUTC   10
#define CAP    96
#define BN_EPS 1e-5f

// ---------------- static device scratch ----------------
__device__ __align__(16) float g_buf0[NN * HC];
__device__ __align__(16) float g_buf1[NN * HC];
__device__ __align__(16) float g_y[NN * NC];
__device__ __align__(16) float g_as[NN * NHD];
__device__ __align__(16) float g_ad[NN * NHD];
__device__ float g_sumL[NL][HC];
__device__ float g_sqL[NL][HC];
__device__ __align__(16) float g_linP[NC * HC];
__device__ float g_const[NC];
__device__ float g_attF[2][HC];
__device__ int   g_deg[NN];
__device__ int   g_pad[NN * CAP];

__device__ __forceinline__ float* bufPtr(int b) { return b ? g_buf1 : g_buf0; }

__device__ __forceinline__ float lrelu_exp(float z) {
    z = (z > 0.f) ? z : 0.2f * z;
    return __expf(z);
}

// ---------------- kernels ----------------

__global__ void k_init(float* __restrict__ out, int out_n, int N) {
    int gid = blockIdx.x * blockDim.x + threadIdx.x;
    if (gid < N) g_deg[gid] = 0;
    if (gid < NL * HC) { (&g_sumL[0][0])[gid] = 0.f; (&g_sqL[0][0])[gid] = 0.f; }
    if (gid < out_n) out[gid] = 0.f;
}

// Block-range fused: [0,nA): embed gather + layer-0 BN stats.  [nA,...): padded-CSR scatter.
__global__ void __launch_bounds__(256)
k_embed_scatter(const int* __restrict__ xidx, const float* __restrict__ embed,
                const int* __restrict__ ei, int N, int E, int nA) {
    int tid = threadIdx.x;
    if ((int)blockIdx.x < nA) {
        __shared__ float sS[2][HC], sQ[2][HC];
        int c = tid & 127, sub = tid >> 7;
        int r0 = blockIdx.x * 64;
        float s = 0.f, s2 = 0.f;
#pragma unroll 4
        for (int it = 0; it < 32; it++) {
            int r = r0 + sub + it * 2;
            if (r < N) {
                float v = embed[xidx[r] * HC + c];
                g_buf0[r * HC + c] = v;
                s += v; s2 += v * v;
            }
        }
        sS[sub][c] = s; sQ[sub][c] = s2;
        __syncthreads();
        if (tid < HC) {
            atomicAdd(&g_sumL[0][tid], sS[0][tid] + sS[1][tid]);
            atomicAdd(&g_sqL[0][tid], sQ[0][tid] + sQ[1][tid]);
        }
    } else {
        int gid = (blockIdx.x - nA) * 256 + tid;
        if (gid < E) {
            int s = ei[gid], d = ei[E + gid];
            int pos = atomicAdd(&g_deg[d], 1);
            g_pad[d * CAP + pos] = s;
        }
    }
}

// Per-layer weight folding (one block).
__global__ void __launch_bounds__(128)
k_prep(int l,
       const float* __restrict__ linW, const float* __restrict__ linb,
       const float* __restrict__ gatW,
       const float* __restrict__ attS, const float* __restrict__ attD,
       const float* __restrict__ bng, const float* __restrict__ bnb, int N) {
    __shared__ float sScale[HC], sShift[HC];
    int tid = threadIdx.x;
    {
        float invN = 1.0f / (float)N;
        float mean = g_sumL[l][tid] * invN;
        float var  = g_sqL[l][tid] * invN - mean * mean;
        float rstd = rsqrtf(var + BN_EPS);
        float sc = bng[l * HC + tid] * rstd;
        sScale[tid] = sc;
        sShift[tid] = bnb[l * HC + tid] - sc * mean;
    }
    __syncthreads();
#pragma unroll
    for (int j = 0; j < 32; j++) {
        int i = tid + j * 128;
        int k = i & 127;
        g_linP[i] = linW[l * NC * HC + i] * sScale[k];
    }
    if (tid < NC) {
        float cst = linb[l * NC + tid];
        const float* lw = &linW[l * NC * HC + tid * HC];
        for (int k = 0; k < HC; k++) cst = fmaf(lw[k], sShift[k], cst);
        g_const[tid] = cst;
    }
    {
        int hd = tid >> 5, cc = tid & 31;
        float a = 0.f, b = 0.f;
        for (int j = 0; j < 32; j++) {
            int r = hd * 32 + j;
            float w = __ldg(&gatW[l * HC * NC + r * NC + cc]);
            a = fmaf(w, __ldg(&attS[l * HC + r]), a);
            b = fmaf(w, __ldg(&attD[l * HC + r]), b);
        }
        g_attF[0][tid] = a;
        g_attF[1][tid] = b;
    }
}

// Per-node GEMM: 32 nodes/block, 128 threads, 4 threads per node (8 channels each).
// Small blocks -> grid 1563 -> ~10 blocks/SM -> latency actually hidden.
__global__ void __launch_bounds__(128)
k_node(int inB, int N) {
    __shared__ __align__(16) float sLinP[NC * HC];     // [c][k]  16 KB
    __shared__ __align__(16) float sX[32 * 33];        // x tile / y staging
    __shared__ float sAs[HC], sAd[HC], sConst[NC];

    int tid = threadIdx.x;
    for (int i = tid; i < NC * HC; i += 128) sLinP[i] = g_linP[i];
    if (tid < HC) { sAs[tid] = g_attF[0][tid]; sAd[tid] = g_attF[1][tid]; }
    if (tid < NC) sConst[tid] = g_const[tid];
    __syncthreads();

    int n0 = blockIdx.x * 32;
    int nd = tid >> 2, p = tid & 3;
    int n = n0 + nd;
    const float* __restrict__ xb = bufPtr(inB);

    float y8[8];
#pragma unroll
    for (int cc = 0; cc < 8; cc++) y8[cc] = sConst[p * 8 + cc];

#pragma unroll
    for (int kt = 0; kt < 4; kt++) {
        __syncthreads();
        // stage 32 nodes x 32 channels (1024 floats), coalesced
#pragma unroll
        for (int j = 0; j < 8; j++) {
            int i = tid + j * 128;
            int ni = i >> 5, ki = i & 31;
            int nn = n0 + ni;
            sX[ni * 33 + ki] = (nn < N) ? xb[nn * HC + kt * 32 + ki] : 0.f;
        }
        __syncthreads();
        float xk[32];
        const float* xr = &sX[nd * 33];
#pragma unroll
        for (int kk = 0; kk < 32; kk++) xk[kk] = xr[kk];
#pragma unroll
        for (int cc = 0; cc < 8; cc++) {
            int c = p * 8 + cc;
            const float4* w4 = reinterpret_cast<const float4*>(&sLinP[c * HC + kt * 32]);
            float acc = y8[cc];
#pragma unroll
            for (int q = 0; q < 8; q++) {
                float4 w = w4[q];
                acc = fmaf(xk[4 * q], w.x, acc);
                acc = fmaf(xk[4 * q + 1], w.y, acc);
                acc = fmaf(xk[4 * q + 2], w.z, acc);
                acc = fmaf(xk[4 * q + 3], w.w, acc);
            }
            y8[cc] = acc;
        }
    }
#pragma unroll
    for (int cc = 0; cc < 8; cc++) y8[cc] = fmaxf(y8[cc], 0.f);

    // attention partial dots over this thread's 8 channels, reduce across the 4-thread group
    float asH[4] = {0.f, 0.f, 0.f, 0.f}, adH[4] = {0.f, 0.f, 0.f, 0.f};
#pragma unroll
    for (int cc = 0; cc < 8; cc++) {
        int c = p * 8 + cc;
        float yv = y8[cc];
#pragma unroll
        for (int h = 0; h < 4; h++) {
            asH[h] = fmaf(yv, sAs[h * 32 + c], asH[h]);
            adH[h] = fmaf(yv, sAd[h * 32 + c], adH[h]);
        }
    }
#pragma unroll
    for (int off = 1; off <= 2; off <<= 1) {
#pragma unroll
        for (int h = 0; h < 4; h++) {
            asH[h] += __shfl_xor_sync(0xffffffffu, asH[h], off);
            adH[h] += __shfl_xor_sync(0xffffffffu, adH[h], off);
        }
    }
    if (p == 0 && n < N) {
        *reinterpret_cast<float4*>(&g_as[n * NHD]) = make_float4(asH[0], asH[1], asH[2], asH[3]);
        *reinterpret_cast<float4*>(&g_ad[n * NHD]) = make_float4(adH[0], adH[1], adH[2], adH[3]);
    }

    // stage y into smem, then coalesced global write
    __syncthreads();
#pragma unroll
    for (int cc = 0; cc < 8; cc++) sX[nd * 33 + p * 8 + cc] = y8[cc];
    __syncthreads();
#pragma unroll
    for (int j = 0; j < 8; j++) {
        int i = tid + j * 128;
        int ni = i >> 5, ci = i & 31;
        int nn = n0 + ni;
        if (nn < N) g_y[nn * NC + ci] = sX[ni * 33 + ci];
    }
}

// Gather: 32 nodes/block, 4 per warp; 4 edges consumed in parallel per warp.
__global__ void __launch_bounds__(256)
k_gather(int outB, const float* __restrict__ gatW, const float* __restrict__ gatb,
         const float* __restrict__ rW, const float* __restrict__ rb,
         const int* __restrict__ batch, float* __restrict__ out,
         int l, int N, int mode) {
    __shared__ __align__(16) float sGatW[HC * 33];
    __shared__ __align__(16) float4 sW[8][32];
    __shared__ int sS[8][32];
    __shared__ __align__(16) float sOut[32][132];
    __shared__ float sRW[OUTC * HC];
    __shared__ float sGatB[HC];

    int tid = threadIdx.x;
    int wid = tid >> 5, lane = tid & 31;
    for (int m = tid; m < HC * NC; m += 256) {
        int r = m >> 5, c = m & 31;
        sGatW[r * 33 + c] = gatW[l * HC * NC + m];
    }
    if (tid < HC) sGatB[tid] = gatb[l * HC + tid];
    if (mode == 1)
        for (int m = tid; m < OUTC * HC; m += 256) sRW[m] = rW[m];
    __syncthreads();

    int hd = lane >> 3, q = lane & 7;
    int grp = lane >> 3;
    const float* __restrict__ ybase = g_y;

#pragma unroll 1
    for (int i4 = 0; i4 < 4; i4++) {
        int nl = wid * 4 + i4;
        int gw = blockIdx.x * 32 + nl;
        bool valid = (gw < N);
        int gws = valid ? gw : 0;

        int cnt = valid ? g_deg[gws] : 0;
        const int* __restrict__ lst = &g_pad[gws * CAP];
        float4 ad4 = make_float4(0.f, 0.f, 0.f, 0.f);
        float4 asSelf = make_float4(0.f, 0.f, 0.f, 0.f);
        if (valid) {
            ad4 = *reinterpret_cast<const float4*>(&g_ad[gws * NHD]);
            asSelf = *reinterpret_cast<const float4*>(&g_as[gws * NHD]);
        }
        float4 wself;
        wself.x = lrelu_exp(asSelf.x + ad4.x);
        wself.y = lrelu_exp(asSelf.y + ad4.y);
        wself.z = lrelu_exp(asSelf.z + ad4.z);
        wself.w = lrelu_exp(asSelf.w + ad4.w);

        float4 accH0 = make_float4(0.f, 0.f, 0.f, 0.f);
        float4 accH1 = make_float4(0.f, 0.f, 0.f, 0.f);
        float4 accH2 = make_float4(0.f, 0.f, 0.f, 0.f);
        float4 accH3 = make_float4(0.f, 0.f, 0.f, 0.f);
        float4 wsum4 = make_float4(0.f, 0.f, 0.f, 0.f);

        for (int base = 0; base < cnt; base += 32) {
            int c2 = min(32, cnt - base);
            int s_l = 0;
            float4 w4 = make_float4(0.f, 0.f, 0.f, 0.f);
            if (lane < c2) {
                s_l = lst[base + lane];
                const float4 as4 = *reinterpret_cast<const float4*>(&g_as[s_l * NHD]);
                w4.x = lrelu_exp(as4.x + ad4.x);
                w4.y = lrelu_exp(as4.y + ad4.y);
                w4.z = lrelu_exp(as4.z + ad4.z);
                w4.w = lrelu_exp(as4.w + ad4.w);
            }
            wsum4.x += w4.x; wsum4.y += w4.y; wsum4.z += w4.z; wsum4.w += w4.w;
            sS[wid][lane] = s_l;
            sW[wid][lane] = w4;
            __syncwarp();

            int j = grp;
            for (; j + 4 < c2; j += 8) {
                int sA = sS[wid][j], sB = sS[wid][j + 4];
                float4 weA = sW[wid][j], weB = sW[wid][j + 4];
                const float4 yA = *reinterpret_cast<const float4*>(&ybase[sA * NC + q * 4]);
                const float4 yB = *reinterpret_cast<const float4*>(&ybase[sB * NC + q * 4]);
                accH0.x = fmaf(weA.x, yA.x, accH0.x); accH0.y = fmaf(weA.x, yA.y, accH0.y);
                accH0.z = fmaf(weA.x, yA.z, accH0.z); accH0.w = fmaf(weA.x, yA.w, accH0.w);
                accH1.x = fmaf(weA.y, yA.x, accH1.x); accH1.y = fmaf(weA.y, yA.y, accH1.y);
                accH1.z = fmaf(weA.y, yA.z, accH1.z); accH1.w = fmaf(weA.y, yA.w, accH1.w);
                accH2.x = fmaf(weA.z, yA.x, accH2.x); accH2.y = fmaf(weA.z, yA.y, accH2.y);
                accH2.z = fmaf(weA.z, yA.z, accH2.z); accH2.w = fmaf(weA.z, yA.w, accH2.w);
                accH3.x = fmaf(weA.w, yA.x, accH3.x); accH3.y = fmaf(weA.w, yA.y, accH3.y);
                accH3.z = fmaf(weA.w, yA.z, accH3.z); accH3.w = fmaf(weA.w, yA.w, accH3.w);
                accH0.x = fmaf(weB.x, yB.x, accH0.x); accH0.y = fmaf(weB.x, yB.y, accH0.y);
                accH0.z = fmaf(weB.x, yB.z, accH0.z); accH0.w = fmaf(weB.x, yB.w, accH0.w);
                accH1.x = fmaf(weB.y, yB.x, accH1.x); accH1.y = fmaf(weB.y, yB.y, accH1.y);
                accH1.z = fmaf(weB.y, yB.z, accH1.z); accH1.w = fmaf(weB.y, yB.w, accH1.w);
                accH2.x = fmaf(weB.z, yB.x, accH2.x); accH2.y = fmaf(weB.z, yB.y, accH2.y);
                accH2.z = fmaf(weB.z, yB.z, accH2.z); accH2.w = fmaf(weB.z, yB.w, accH2.w);
                accH3.x = fmaf(weB.w, yB.x, accH3.x); accH3.y = fmaf(weB.w, yB.y, accH3.y);
                accH3.z = fmaf(weB.w, yB.z, accH3.z); accH3.w = fmaf(weB.w, yB.w, accH3.w);
            }
            if (j < c2) {
                int sA = sS[wid][j];
                float4 weA = sW[wid][j];
                const float4 yA = *reinterpret_cast<const float4*>(&ybase[sA * NC + q * 4]);
                accH0.x = fmaf(weA.x, yA.x, accH0.x); accH0.y = fmaf(weA.x, yA.y, accH0.y);
                accH0.z = fmaf(weA.x, yA.z, accH0.z); accH0.w = fmaf(weA.x, yA.w, accH0.w);
                accH1.x = fmaf(weA.y, yA.x, accH1.x); accH1.y = fmaf(weA.y, yA.y, accH1.y);
                accH1.z = fmaf(weA.y, yA.z, accH1.z); accH1.w = fmaf(weA.y, yA.w, accH1.w);
                accH2.x = fmaf(weA.z, yA.x, accH2.x); accH2.y = fmaf(weA.z, yA.y, accH2.y);
                accH2.z = fmaf(weA.z, yA.z, accH2.z); accH2.w = fmaf(weA.z, yA.w, accH2.w);
                accH3.x = fmaf(weA.w, yA.x, accH3.x); accH3.y = fmaf(weA.w, yA.y, accH3.y);
                accH3.z = fmaf(weA.w, yA.z, accH3.z); accH3.w = fmaf(weA.w, yA.w, accH3.w);
            }
            __syncwarp();
        }

#pragma unroll
        for (int off = 8; off <= 16; off <<= 1) {
            accH0.x += __shfl_xor_sync(0xffffffffu, accH0.x, off);
            accH0.y += __shfl_xor_sync(0xffffffffu, accH0.y, off);
            accH0.z += __shfl_xor_sync(0xffffffffu, accH0.z, off);
            accH0.w += __shfl_xor_sync(0xffffffffu, accH0.w, off);
            accH1.x += __shfl_xor_sync(0xffffffffu, accH1.x, off);
            accH1.y += __shfl_xor_sync(0xffffffffu, accH1.y, off);
            accH1.z += __shfl_xor_sync(0xffffffffu, accH1.z, off);
            accH1.w += __shfl_xor_sync(0xffffffffu, accH1.w, off);
            accH2.x += __shfl_xor_sync(0xffffffffu, accH2.x, off);
            accH2.y += __shfl_xor_sync(0xffffffffu, accH2.y, off);
            accH2.z += __shfl_xor_sync(0xffffffffu, accH2.z, off);
            accH2.w += __shfl_xor_sync(0xffffffffu, accH2.w, off);
            accH3.x += __shfl_xor_sync(0xffffffffu, accH3.x, off);
            accH3.y += __shfl_xor_sync(0xffffffffu, accH3.y, off);
            accH3.z += __shfl_xor_sync(0xffffffffu, accH3.z, off);
            accH3.w += __shfl_xor_sync(0xffffffffu, accH3.w, off);
        }
        float4 acc = (hd == 0) ? accH0 : (hd == 1) ? accH1 : (hd == 2) ? accH2 : accH3;

#pragma unroll
        for (int off = 16; off; off >>= 1) {
            wsum4.x += __shfl_xor_sync(0xffffffffu, wsum4.x, off);
            wsum4.y += __shfl_xor_sync(0xffffffffu, wsum4.y, off);
            wsum4.z += __shfl_xor_sync(0xffffffffu, wsum4.z, off);
            wsum4.w += __shfl_xor_sync(0xffffffffu, wsum4.w, off);
        }
        wsum4.x += wself.x; wsum4.y += wself.y; wsum4.z += wself.z; wsum4.w += wself.w;
        float wsh = (hd == 0) ? wself.x : (hd == 1) ? wself.y : (hd == 2) ? wself.z : wself.w;
        const float4 ys = *reinterpret_cast<const float4*>(&ybase[gws * NC + q * 4]);
        acc.x = fmaf(wsh, ys.x, acc.x); acc.y = fmaf(wsh, ys.y, acc.y);
        acc.z = fmaf(wsh, ys.z, acc.z); acc.w = fmaf(wsh, ys.w, acc.w);
        float wsumh = (hd == 0) ? wsum4.x : (hd == 1) ? wsum4.y : (hd == 2) ? wsum4.z : wsum4.w;
        float inv = 1.f / (wsumh + 1e-16f);
        acc.x *= inv; acc.y *= inv; acc.z *= inv; acc.w *= inv;

        *reinterpret_cast<float4*>(&sOut[nl][lane * 4]) = acc;
        __syncwarp();

        float a[4];
#pragma unroll
        for (int i = 0; i < 4; i++) {
            int o = lane + 32 * i;
            float v = sGatB[o];
            const float* aggh = &sOut[nl][i * 32];
            const float* wrow = &sGatW[o * 33];
#pragma unroll
            for (int c = 0; c < 32; c++) v = fmaf(wrow[c], aggh[c], v);
            a[i] = valid ? v : 0.f;
        }
        __syncwarp();
#pragma unroll
        for (int i = 0; i < 4; i++) sOut[nl][lane + 32 * i] = a[i];

        if (mode == 0) {
            if (valid) {
                float* outrow = bufPtr(outB) + gw * HC;
#pragma unroll
                for (int i = 0; i < 4; i++) outrow[lane + 32 * i] = a[i];
            }
        } else if (valid) {
            int g = batch[gw];
#pragma unroll
            for (int o = 0; o < OUTC; o++) {
                float pdot = 0.f;
#pragma unroll
                for (int i = 0; i < 4; i++)
                    pdot = fmaf(a[i], sRW[o * HC + lane + 32 * i], pdot);
#pragma unroll
                for (int off = 16; off; off >>= 1)
                    pdot += __shfl_xor_sync(0xffffffffu, pdot, off);
                if (lane == o) atomicAdd(&out[g * OUTC + o], pdot + __ldg(&rb[o]));
            }
        }
    }

    if (mode == 0) {
        __syncthreads();
        if (tid < HC) {
            float s = 0.f, s2 = 0.f;
#pragma unroll
            for (int w = 0; w < 32; w++) {
                float v = sOut[w][tid];
                s += v; s2 += v * v;
            }
            atomicAdd(&g_sumL[l + 1][tid], s);
            atomicAdd(&g_sqL[l + 1][tid], s2);
        }
    }
}

// ---------------- launch ----------------
extern "C" void kernel_launch(void* const* d_in, const int* in_sizes, int n_in,
                              void* d_out, int out_size) {
    const int*   xidx  = (const int*)d_in[0];
    const int*   ei    = (const int*)d_in[1];
    const int*   batch = (const int*)d_in[2];
    const float* embed = (const float*)d_in[3];
    const float* bng   = (const float*)d_in[4];
    const float* bnb   = (const float*)d_in[5];
    const float* linW  = (const float*)d_in[6];
    const float* linb  = (const float*)d_in[7];
    const float* gatW  = (const float*)d_in[8];
    const float* attS  = (const float*)d_in[9];
    const float* attD  = (const float*)d_in[10];
    const float* gatb  = (const float*)d_in[11];
    const float* rW    = (const float*)d_in[12];
    const float* rb    = (const float*)d_in[13];
    float* out = (float*)d_out;

    int N = in_sizes[0];
    int E = in_sizes[1] / 2;
    int nA = (N + 63) / 64;
    int nB = (E + 255) / 256;

    k_init<<<(N + 255) / 256, 256>>>(out, out_size, N);
    k_embed_scatter<<<nA + nB, 256>>>(xidx, embed, ei, N, E, nA);

    for (int l = 0; l < NL; l++) {
        int inB = l & 1;
        int outB = inB ^ 1;
        int mode = (l == NL - 1) ? 1 : 0;
        k_prep<<<1, 128>>>(l, linW, linb, gatW, attS, attD, bng, bnb, N);
        k_node<<<(N + 31) / 32, 128>>>(inB, N);
        k_gather<<<(N + 31) / 32, 256>>>(outB, gatW, gatb, rW, rb, batch, out, l, N, mode);
    }
}

// round 10
// speedup vs baseline: 1.5448x; 1.4710x over previous
#include <cuda_runtime.h>

#define NN     50000
#define EE     800000
#define NHD    4
#define NC     32
#define HC     128
#define NL     3
#define OUTC   10
#define CAP    96
#define BN_EPS 1e-5f

// ---------------- static device scratch ----------------
__device__ __align__(16) float g_buf0[NN * HC];
__device__ __align__(16) float g_buf1[NN * HC];
__device__ __align__(16) float g_y[NN * NC];
__device__ __align__(16) float g_as[NN * NHD];
__device__ __align__(16) float g_ad[NN * NHD];
__device__ float g_sumL[NL][HC];
__device__ float g_sqL[NL][HC];
__device__ __align__(16) float g_linP[NC * HC];
__device__ float g_const[NC];
__device__ float g_attF[2][HC];
__device__ int   g_deg[NN];
__device__ int   g_pad[NN * CAP];

__device__ __forceinline__ float* bufPtr(int b) { return b ? g_buf1 : g_buf0; }

__device__ __forceinline__ float lrelu_exp(float z) {
    z = (z > 0.f) ? z : 0.2f * z;
    return __expf(z);
}

// ---------------- kernels ----------------

__global__ void k_init(float* __restrict__ out, int out_n, int N) {
    int gid = blockIdx.x * blockDim.x + threadIdx.x;
    if (gid < N) g_deg[gid] = 0;
    if (gid < NL * HC) { (&g_sumL[0][0])[gid] = 0.f; (&g_sqL[0][0])[gid] = 0.f; }
    if (gid < out_n) out[gid] = 0.f;
}

// Block-range fused: [0,nA): embed gather + layer-0 BN stats.  [nA,...): padded-CSR scatter.
__global__ void __launch_bounds__(256)
k_embed_scatter(const int* __restrict__ xidx, const float* __restrict__ embed,
                const int* __restrict__ ei, int N, int E, int nA) {
    int tid = threadIdx.x;
    if ((int)blockIdx.x < nA) {
        __shared__ float sS[2][HC], sQ[2][HC];
        int c = tid & 127, sub = tid >> 7;
        int r0 = blockIdx.x * 64;
        float s = 0.f, s2 = 0.f;
#pragma unroll 4
        for (int it = 0; it < 32; it++) {
            int r = r0 + sub + it * 2;
            if (r < N) {
                float v = embed[xidx[r] * HC + c];
                g_buf0[r * HC + c] = v;
                s += v; s2 += v * v;
            }
        }
        sS[sub][c] = s; sQ[sub][c] = s2;
        __syncthreads();
        if (tid < HC) {
            atomicAdd(&g_sumL[0][tid], sS[0][tid] + sS[1][tid]);
            atomicAdd(&g_sqL[0][tid], sQ[0][tid] + sQ[1][tid]);
        }
    } else {
        int gid = (blockIdx.x - nA) * 256 + tid;
        if (gid < E) {
            int s = ei[gid], d = ei[E + gid];
            int pos = atomicAdd(&g_deg[d], 1);
            g_pad[d * CAP + pos] = s;
        }
    }
}

// Per-layer weight folding (one block).
__global__ void __launch_bounds__(128)
k_prep(int l,
       const float* __restrict__ linW, const float* __restrict__ linb,
       const float* __restrict__ gatW,
       const float* __restrict__ attS, const float* __restrict__ attD,
       const float* __restrict__ bng, const float* __restrict__ bnb, int N) {
    __shared__ float sScale[HC], sShift[HC];
    int tid = threadIdx.x;
    {
        float invN = 1.0f / (float)N;
        float mean = g_sumL[l][tid] * invN;
        float var  = g_sqL[l][tid] * invN - mean * mean;
        float rstd = rsqrtf(var + BN_EPS);
        float sc = bng[l * HC + tid] * rstd;
        sScale[tid] = sc;
        sShift[tid] = bnb[l * HC + tid] - sc * mean;
    }
    __syncthreads();
#pragma unroll
    for (int j = 0; j < 32; j++) {
        int i = tid + j * 128;
        int k = i & 127;
        g_linP[i] = linW[l * NC * HC + i] * sScale[k];
    }
    if (tid < NC) {
        float cst = linb[l * NC + tid];
        const float* lw = &linW[l * NC * HC + tid * HC];
        for (int k = 0; k < HC; k++) cst = fmaf(lw[k], sShift[k], cst);
        g_const[tid] = cst;
    }
    {
        int hd = tid >> 5, cc = tid & 31;
        float a = 0.f, b = 0.f;
        for (int j = 0; j < 32; j++) {
            int r = hd * 32 + j;
            float w = __ldg(&gatW[l * HC * NC + r * NC + cc]);
            a = fmaf(w, __ldg(&attS[l * HC + r]), a);
            b = fmaf(w, __ldg(&attD[l * HC + r]), b);
        }
        g_attF[0][tid] = a;
        g_attF[1][tid] = b;
    }
}

// Per-node GEMM: one thread per node, 128 nodes/block. Weight LDS are
// warp-uniform (1-phase broadcast); x-tile loads vectorized (stride-36 rows).
__global__ void __launch_bounds__(128)
k_node(int inB, int N) {
    __shared__ __align__(16) float sLinP[NC * HC];   // [c][k], 16 KB, uniform reads
    __shared__ __align__(16) float sX[128 * 36];     // x tile [node][k] / y staging
    __shared__ float sAs[HC], sAd[HC], sConst[NC];

    int tid = threadIdx.x;
    for (int i = tid; i < NC * HC; i += 128) sLinP[i] = g_linP[i];
    if (tid < HC) { sAs[tid] = g_attF[0][tid]; sAd[tid] = g_attF[1][tid]; }
    if (tid < NC) sConst[tid] = g_const[tid];
    __syncthreads();

    int n0 = blockIdx.x * 128;
    int n = n0 + tid;
    const float* __restrict__ xb = bufPtr(inB);

    float y[NC];
#pragma unroll
    for (int c = 0; c < NC; c++) y[c] = sConst[c];

#pragma unroll
    for (int kt = 0; kt < 4; kt++) {
        __syncthreads();
        // stage 128 nodes x 32 ch, coalesced global reads; row stride 36 (16B-aligned)
#pragma unroll
        for (int j = 0; j < 32; j++) {
            int i = tid + j * 128;
            int ni = i >> 5, ki = i & 31;
            int nn = n0 + ni;
            sX[ni * 36 + ki] = (nn < N) ? xb[nn * HC + kt * 32 + ki] : 0.f;
        }
        __syncthreads();
        float xk[32];
        const float4* xr = reinterpret_cast<const float4*>(&sX[tid * 36]);
#pragma unroll
        for (int kk = 0; kk < 8; kk++) {
            float4 v = xr[kk];   // lanes stride 9 f4 -> conflict-free
            xk[kk * 4] = v.x; xk[kk * 4 + 1] = v.y;
            xk[kk * 4 + 2] = v.z; xk[kk * 4 + 3] = v.w;
        }
#pragma unroll
        for (int c = 0; c < NC; c++) {
            const float4* w4 = reinterpret_cast<const float4*>(&sLinP[c * HC + kt * 32]);
            float acc = y[c];
#pragma unroll
            for (int q = 0; q < 8; q++) {
                float4 w = w4[q];   // warp-uniform address -> broadcast
                acc = fmaf(xk[4 * q], w.x, acc);
                acc = fmaf(xk[4 * q + 1], w.y, acc);
                acc = fmaf(xk[4 * q + 2], w.z, acc);
                acc = fmaf(xk[4 * q + 3], w.w, acc);
            }
            y[c] = acc;
        }
    }
#pragma unroll
    for (int c = 0; c < NC; c++) y[c] = fmaxf(y[c], 0.f);

    // attention logits (uniform sAs/sAd reads)
    if (n < N) {
        float as[NHD] = {0.f, 0.f, 0.f, 0.f}, ad[NHD] = {0.f, 0.f, 0.f, 0.f};
#pragma unroll
        for (int hd = 0; hd < NHD; hd++) {
#pragma unroll
            for (int c = 0; c < NC; c++) {
                as[hd] = fmaf(y[c], sAs[hd * 32 + c], as[hd]);
                ad[hd] = fmaf(y[c], sAd[hd * 32 + c], ad[hd]);
            }
        }
        *reinterpret_cast<float4*>(&g_as[n * NHD]) = make_float4(as[0], as[1], as[2], as[3]);
        *reinterpret_cast<float4*>(&g_ad[n * NHD]) = make_float4(ad[0], ad[1], ad[2], ad[3]);
    }

    // y staging (stride-33: conflict-free scalar) then coalesced global write
    __syncthreads();
#pragma unroll
    for (int c = 0; c < NC; c++) sX[tid * 33 + c] = y[c];
    __syncthreads();
#pragma unroll
    for (int j = 0; j < 32; j++) {
        int i = tid + j * 128;
        int ni = i >> 5, ci = i & 31;
        int nn = n0 + ni;
        if (nn < N) g_y[nn * NC + ci] = sX[ni * 33 + ci];
    }
}

// Gather: 32 nodes/block, 4 per warp; 4 edges consumed in parallel per warp.
__global__ void __launch_bounds__(256)
k_gather(int outB, const float* __restrict__ gatW, const float* __restrict__ gatb,
         const float* __restrict__ rW, const float* __restrict__ rb,
         const int* __restrict__ batch, float* __restrict__ out,
         int l, int N, int mode) {
    __shared__ __align__(16) float sGatW[HC * 33];
    __shared__ __align__(16) float4 sW[8][32];
    __shared__ int sS[8][32];
    __shared__ __align__(16) float sOut[32][132];
    __shared__ float sRW[OUTC * HC];
    __shared__ float sGatB[HC];

    int tid = threadIdx.x;
    int wid = tid >> 5, lane = tid & 31;
    for (int m = tid; m < HC * NC; m += 256) {
        int r = m >> 5, c = m & 31;
        sGatW[r * 33 + c] = gatW[l * HC * NC + m];
    }
    if (tid < HC) sGatB[tid] = gatb[l * HC + tid];
    if (mode == 1)
        for (int m = tid; m < OUTC * HC; m += 256) sRW[m] = rW[m];
    __syncthreads();

    int hd = lane >> 3, q = lane & 7;
    int grp = lane >> 3;
    const float* __restrict__ ybase = g_y;

#pragma unroll 1
    for (int i4 = 0; i4 < 4; i4++) {
        int nl = wid * 4 + i4;
        int gw = blockIdx.x * 32 + nl;
        bool valid = (gw < N);
        int gws = valid ? gw : 0;

        int cnt = valid ? g_deg[gws] : 0;
        const int* __restrict__ lst = &g_pad[gws * CAP];
        float4 ad4 = make_float4(0.f, 0.f, 0.f, 0.f);
        float4 asSelf = make_float4(0.f, 0.f, 0.f, 0.f);
        if (valid) {
            ad4 = *reinterpret_cast<const float4*>(&g_ad[gws * NHD]);
            asSelf = *reinterpret_cast<const float4*>(&g_as[gws * NHD]);
        }
        float4 wself;
        wself.x = lrelu_exp(asSelf.x + ad4.x);
        wself.y = lrelu_exp(asSelf.y + ad4.y);
        wself.z = lrelu_exp(asSelf.z + ad4.z);
        wself.w = lrelu_exp(asSelf.w + ad4.w);

        float4 accH0 = make_float4(0.f, 0.f, 0.f, 0.f);
        float4 accH1 = make_float4(0.f, 0.f, 0.f, 0.f);
        float4 accH2 = make_float4(0.f, 0.f, 0.f, 0.f);
        float4 accH3 = make_float4(0.f, 0.f, 0.f, 0.f);
        float4 wsum4 = make_float4(0.f, 0.f, 0.f, 0.f);

        for (int base = 0; base < cnt; base += 32) {
            int c2 = min(32, cnt - base);
            int s_l = 0;
            float4 w4 = make_float4(0.f, 0.f, 0.f, 0.f);
            if (lane < c2) {
                s_l = lst[base + lane];
                const float4 as4 = *reinterpret_cast<const float4*>(&g_as[s_l * NHD]);
                w4.x = lrelu_exp(as4.x + ad4.x);
                w4.y = lrelu_exp(as4.y + ad4.y);
                w4.z = lrelu_exp(as4.z + ad4.z);
                w4.w = lrelu_exp(as4.w + ad4.w);
            }
            wsum4.x += w4.x; wsum4.y += w4.y; wsum4.z += w4.z; wsum4.w += w4.w;
            sS[wid][lane] = s_l;
            sW[wid][lane] = w4;
            __syncwarp();

            int j = grp;
            for (; j + 4 < c2; j += 8) {
                int sA = sS[wid][j], sB = sS[wid][j + 4];
                float4 weA = sW[wid][j], weB = sW[wid][j + 4];
                const float4 yA = *reinterpret_cast<const float4*>(&ybase[sA * NC + q * 4]);
                const float4 yB = *reinterpret_cast<const float4*>(&ybase[sB * NC + q * 4]);
                accH0.x = fmaf(weA.x, yA.x, accH0.x); accH0.y = fmaf(weA.x, yA.y, accH0.y);
                accH0.z = fmaf(weA.x, yA.z, accH0.z); accH0.w = fmaf(weA.x, yA.w, accH0.w);
                accH1.x = fmaf(weA.y, yA.x, accH1.x); accH1.y = fmaf(weA.y, yA.y, accH1.y);
                accH1.z = fmaf(weA.y, yA.z, accH1.z); accH1.w = fmaf(weA.y, yA.w, accH1.w);
                accH2.x = fmaf(weA.z, yA.x, accH2.x); accH2.y = fmaf(weA.z, yA.y, accH2.y);
                accH2.z = fmaf(weA.z, yA.z, accH2.z); accH2.w = fmaf(weA.z, yA.w, accH2.w);
                accH3.x = fmaf(weA.w, yA.x, accH3.x); accH3.y = fmaf(weA.w, yA.y, accH3.y);
                accH3.z = fmaf(weA.w, yA.z, accH3.z); accH3.w = fmaf(weA.w, yA.w, accH3.w);
                accH0.x = fmaf(weB.x, yB.x, accH0.x); accH0.y = fmaf(weB.x, yB.y, accH0.y);
                accH0.z = fmaf(weB.x, yB.z, accH0.z); accH0.w = fmaf(weB.x, yB.w, accH0.w);
                accH1.x = fmaf(weB.y, yB.x, accH1.x); accH1.y = fmaf(weB.y, yB.y, accH1.y);
                accH1.z = fmaf(weB.y, yB.z, accH1.z); accH1.w = fmaf(weB.y, yB.w, accH1.w);
                accH2.x = fmaf(weB.z, yB.x, accH2.x); accH2.y = fmaf(weB.z, yB.y, accH2.y);
                accH2.z = fmaf(weB.z, yB.z, accH2.z); accH2.w = fmaf(weB.z, yB.w, accH2.w);
                accH3.x = fmaf(weB.w, yB.x, accH3.x); accH3.y = fmaf(weB.w, yB.y, accH3.y);
                accH3.z = fmaf(weB.w, yB.z, accH3.z); accH3.w = fmaf(weB.w, yB.w, accH3.w);
            }
            if (j < c2) {
                int sA = sS[wid][j];
                float4 weA = sW[wid][j];
                const float4 yA = *reinterpret_cast<const float4*>(&ybase[sA * NC + q * 4]);
                accH0.x = fmaf(weA.x, yA.x, accH0.x); accH0.y = fmaf(weA.x, yA.y, accH0.y);
                accH0.z = fmaf(weA.x, yA.z, accH0.z); accH0.w = fmaf(weA.x, yA.w, accH0.w);
                accH1.x = fmaf(weA.y, yA.x, accH1.x); accH1.y = fmaf(weA.y, yA.y, accH1.y);
                accH1.z = fmaf(weA.y, yA.z, accH1.z); accH1.w = fmaf(weA.y, yA.w, accH1.w);
                accH2.x = fmaf(weA.z, yA.x, accH2.x); accH2.y = fmaf(weA.z, yA.y, accH2.y);
                accH2.z = fmaf(weA.z, yA.z, accH2.z); accH2.w = fmaf(weA.z, yA.w, accH2.w);
                accH3.x = fmaf(weA.w, yA.x, accH3.x); accH3.y = fmaf(weA.w, yA.y, accH3.y);
                accH3.z = fmaf(weA.w, yA.z, accH3.z); accH3.w = fmaf(weA.w, yA.w, accH3.w);
            }
            __syncwarp();
        }

#pragma unroll
        for (int off = 8; off <= 16; off <<= 1) {
            accH0.x += __shfl_xor_sync(0xffffffffu, accH0.x, off);
            accH0.y += __shfl_xor_sync(0xffffffffu, accH0.y, off);
            accH0.z += __shfl_xor_sync(0xffffffffu, accH0.z, off);
            accH0.w += __shfl_xor_sync(0xffffffffu, accH0.w, off);
            accH1.x += __shfl_xor_sync(0xffffffffu, accH1.x, off);
            accH1.y += __shfl_xor_sync(0xffffffffu, accH1.y, off);
            accH1.z += __shfl_xor_sync(0xffffffffu, accH1.z, off);
            accH1.w += __shfl_xor_sync(0xffffffffu, accH1.w, off);
            accH2.x += __shfl_xor_sync(0xffffffffu, accH2.x, off);
            accH2.y += __shfl_xor_sync(0xffffffffu, accH2.y, off);
            accH2.z += __shfl_xor_sync(0xffffffffu, accH2.z, off);
            accH2.w += __shfl_xor_sync(0xffffffffu, accH2.w, off);
            accH3.x += __shfl_xor_sync(0xffffffffu, accH3.x, off);
            accH3.y += __shfl_xor_sync(0xffffffffu, accH3.y, off);
            accH3.z += __shfl_xor_sync(0xffffffffu, accH3.z, off);
            accH3.w += __shfl_xor_sync(0xffffffffu, accH3.w, off);
        }
        float4 acc = (hd == 0) ? accH0 : (hd == 1) ? accH1 : (hd == 2) ? accH2 : accH3;

#pragma unroll
        for (int off = 16; off; off >>= 1) {
            wsum4.x += __shfl_xor_sync(0xffffffffu, wsum4.x, off);
            wsum4.y += __shfl_xor_sync(0xffffffffu, wsum4.y, off);
            wsum4.z += __shfl_xor_sync(0xffffffffu, wsum4.z, off);
            wsum4.w += __shfl_xor_sync(0xffffffffu, wsum4.w, off);
        }
        wsum4.x += wself.x; wsum4.y += wself.y; wsum4.z += wself.z; wsum4.w += wself.w;
        float wsh = (hd == 0) ? wself.x : (hd == 1) ? wself.y : (hd == 2) ? wself.z : wself.w;
        const float4 ys = *reinterpret_cast<const float4*>(&ybase[gws * NC + q * 4]);
        acc.x = fmaf(wsh, ys.x, acc.x); acc.y = fmaf(wsh, ys.y, acc.y);
        acc.z = fmaf(wsh, ys.z, acc.z); acc.w = fmaf(wsh, ys.w, acc.w);
        float wsumh = (hd == 0) ? wsum4.x : (hd == 1) ? wsum4.y : (hd == 2) ? wsum4.z : wsum4.w;
        float inv = 1.f / (wsumh + 1e-16f);
        acc.x *= inv; acc.y *= inv; acc.z *= inv; acc.w *= inv;

        *reinterpret_cast<float4*>(&sOut[nl][lane * 4]) = acc;
        __syncwarp();

        float a[4];
#pragma unroll
        for (int i = 0; i < 4; i++) {
            int o = lane + 32 * i;
            float v = sGatB[o];
            const float* aggh = &sOut[nl][i * 32];
            const float* wrow = &sGatW[o * 33];
#pragma unroll
            for (int c = 0; c < 32; c++) v = fmaf(wrow[c], aggh[c], v);
            a[i] = valid ? v : 0.f;
        }
        __syncwarp();
#pragma unroll
        for (int i = 0; i < 4; i++) sOut[nl][lane + 32 * i] = a[i];

        if (mode == 0) {
            if (valid) {
                float* outrow = bufPtr(outB) + gw * HC;
#pragma unroll
                for (int i = 0; i < 4; i++) outrow[lane + 32 * i] = a[i];
            }
        } else if (valid) {
            int g = batch[gw];
#pragma unroll
            for (int o = 0; o < OUTC; o++) {
                float pdot = 0.f;
#pragma unroll
                for (int i = 0; i < 4; i++)
                    pdot = fmaf(a[i], sRW[o * HC + lane + 32 * i], pdot);
#pragma unroll
                for (int off = 16; off; off >>= 1)
                    pdot += __shfl_xor_sync(0xffffffffu, pdot, off);
                if (lane == o) atomicAdd(&out[g * OUTC + o], pdot + __ldg(&rb[o]));
            }
        }
    }

    if (mode == 0) {
        __syncthreads();
        if (tid < HC) {
            float s = 0.f, s2 = 0.f;
#pragma unroll
            for (int w = 0; w < 32; w++) {
                float v = sOut[w][tid];
                s += v; s2 += v * v;
            }
            atomicAdd(&g_sumL[l + 1][tid], s);
            atomicAdd(&g_sqL[l + 1][tid], s2);
        }
    }
}

// ---------------- launch ----------------
extern "C" void kernel_launch(void* const* d_in, const int* in_sizes, int n_in,
                              void* d_out, int out_size) {
    const int*   xidx  = (const int*)d_in[0];
    const int*   ei    = (const int*)d_in[1];
    const int*   batch = (const int*)d_in[2];
    const float* embed = (const float*)d_in[3];
    const float* bng   = (const float*)d_in[4];
    const float* bnb   = (const float*)d_in[5];
    const float* linW  = (const float*)d_in[6];
    const float* linb  = (const float*)d_in[7];
    const float* gatW  = (const float*)d_in[8];
    const float* attS  = (const float*)d_in[9];
    const float* attD  = (const float*)d_in[10];
    const float* gatb  = (const float*)d_in[11];
    const float* rW    = (const float*)d_in[12];
    const float* rb    = (const float*)d_in[13];
    float* out = (float*)d_out;

    int N = in_sizes[0];
    int E = in_sizes[1] / 2;
    int nA = (N + 63) / 64;
    int nB = (E + 255) / 256;

    k_init<<<(N + 255) / 256, 256>>>(out, out_size, N);
    k_embed_scatter<<<nA + nB, 256>>>(xidx, embed, ei, N, E, nA);

    for (int l = 0; l < NL; l++) {
        int inB = l & 1;
        int outB = inB ^ 1;
        int mode = (l == NL - 1) ? 1 : 0;
        k_prep<<<1, 128>>>(l, linW, linb, gatW, attS, attD, bng, bnb, N);
        k_node<<<(N + 127) / 128, 128>>>(inB, N);
        k_gather<<<(N + 31) / 32, 256>>>(outB, gatW, gatb, rW, rb, batch, out, l, N, mode);
    }
}

// round 11
// speedup vs baseline: 1.6390x; 1.0610x over previous
#include <cuda_runtime.h>

#define NN     50000
#define NP     50048          // padded node stride for channel-major buffers
#define EE     800000
#define NHD    4
#define NC     32
#define HC     128
#define NL     3
#define OUTC   10
#define CAP    96
#define BN_EPS 1e-5f

// ---------------- static device scratch ----------------
// Inter-layer node features are CHANNEL-MAJOR: buf[c*NP + n]
__device__ __align__(16) float g_buf0[HC * NP];
__device__ __align__(16) float g_buf1[HC * NP];
__device__ __align__(16) float g_y[NN * NC];        // row-major (gather reads rows)
__device__ __align__(16) float g_as[NN * NHD];
__device__ __align__(16) float g_ad[NN * NHD];
__device__ float g_sumL[NL][HC];
__device__ float g_sqL[NL][HC];
__device__ __align__(16) float g_linT[HC * NC];     // folded lin_W, transposed [k][c]
__device__ float g_const[NC];
__device__ float g_attF[2][HC];
__device__ int   g_deg[NN];
__device__ int   g_pad[NN * CAP];

__device__ __forceinline__ float* bufPtr(int b) { return b ? g_buf1 : g_buf0; }

__device__ __forceinline__ float lrelu_exp(float z) {
    z = (z > 0.f) ? z : 0.2f * z;
    return __expf(z);
}

// ---------------- kernels ----------------

__global__ void k_init(float* __restrict__ out, int out_n, int N) {
    int gid = blockIdx.x * blockDim.x + threadIdx.x;
    if (gid < N) g_deg[gid] = 0;
    if (gid < NL * HC) { (&g_sumL[0][0])[gid] = 0.f; (&g_sqL[0][0])[gid] = 0.f; }
    if (gid < out_n) out[gid] = 0.f;
}

// Block-range fused: [0,nA): embed gather (-> channel-major buf0) + layer-0 BN stats.
// [nA,...): padded-CSR scatter.
__global__ void __launch_bounds__(256)
k_embed_scatter(const int* __restrict__ xidx, const float* __restrict__ embed,
                const int* __restrict__ ei, int N, int E, int nA) {
    int tid = threadIdx.x;
    if ((int)blockIdx.x < nA) {
        __shared__ float sS[2][HC], sQ[2][HC];
        __shared__ float sT[64][129];     // 64 nodes x 128 ch transpose tile
        int c = tid & 127, sub = tid >> 7;
        int r0 = blockIdx.x * 64;
        float s = 0.f, s2 = 0.f;
#pragma unroll 4
        for (int it = 0; it < 32; it++) {
            int rl = sub + it * 2;
            int r = r0 + rl;
            float v = 0.f;
            if (r < N) {
                v = embed[xidx[r] * HC + c];
                s += v; s2 += v * v;
            }
            sT[rl][c] = v;
        }
        sS[sub][c] = s; sQ[sub][c] = s2;
        __syncthreads();
        if (tid < HC) {
            atomicAdd(&g_sumL[0][tid], sS[0][tid] + sS[1][tid]);
            atomicAdd(&g_sqL[0][tid], sQ[0][tid] + sQ[1][tid]);
        }
        // transposed write: channel-major
        int node = tid & 63;
        int cb = tid >> 6;                // 0..3
        int r = r0 + node;
        if (r < N) {
#pragma unroll
            for (int p = 0; p < 32; p++) {
                int cc = cb * 32 + p;
                g_buf0[cc * NP + r] = sT[node][cc];
            }
        }
    } else {
        int gid = (blockIdx.x - nA) * 256 + tid;
        if (gid < E) {
            int s = ei[gid], d = ei[E + gid];
            int pos = atomicAdd(&g_deg[d], 1);
            g_pad[d * CAP + pos] = s;
        }
    }
}

// Per-layer weight folding (one block). linW folded+transposed to [k][c].
__global__ void __launch_bounds__(128)
k_prep(int l,
       const float* __restrict__ linW, const float* __restrict__ linb,
       const float* __restrict__ gatW,
       const float* __restrict__ attS, const float* __restrict__ attD,
       const float* __restrict__ bng, const float* __restrict__ bnb, int N) {
    __shared__ float sScale[HC], sShift[HC];
    int tid = threadIdx.x;
    {
        float invN = 1.0f / (float)N;
        float mean = g_sumL[l][tid] * invN;
        float var  = g_sqL[l][tid] * invN - mean * mean;
        float rstd = rsqrtf(var + BN_EPS);
        float sc = bng[l * HC + tid] * rstd;
        sScale[tid] = sc;
        sShift[tid] = bnb[l * HC + tid] - sc * mean;
    }
    __syncthreads();
#pragma unroll
    for (int j = 0; j < 32; j++) {
        int i = tid + j * 128;
        int c = i >> 7, k = i & 127;
        g_linT[k * NC + c] = linW[l * NC * HC + i] * sScale[k];
    }
    if (tid < NC) {
        float cst = linb[l * NC + tid];
        const float* lw = &linW[l * NC * HC + tid * HC];
        for (int k = 0; k < HC; k++) cst = fmaf(lw[k], sShift[k], cst);
        g_const[tid] = cst;
    }
    {
        int hd = tid >> 5, cc = tid & 31;
        float a = 0.f, b = 0.f;
        for (int j = 0; j < 32; j++) {
            int r = hd * 32 + j;
            float w = __ldg(&gatW[l * HC * NC + r * NC + cc]);
            a = fmaf(w, __ldg(&attS[l * HC + r]), a);
            b = fmaf(w, __ldg(&attD[l * HC + r]), b);
        }
        g_attF[0][tid] = a;
        g_attF[1][tid] = b;
    }
}

// Per-node GEMM: one thread per node, channel-major x -> directly coalesced LDG,
// warp-uniform weight broadcasts, no staging barriers in the main loop.
__global__ void __launch_bounds__(128)
k_node(int inB, int N) {
    __shared__ __align__(16) float sLinT[HC * NC];   // [k][c], uniform reads
    __shared__ __align__(16) float sY[128 * 33];     // y staging for coalesced write
    __shared__ float sAs[HC], sAd[HC], sConst[NC];

    int tid = threadIdx.x;
    for (int i = tid; i < HC * NC; i += 128) sLinT[i] = g_linT[i];
    if (tid < HC) { sAs[tid] = g_attF[0][tid]; sAd[tid] = g_attF[1][tid]; }
    if (tid < NC) sConst[tid] = g_const[tid];
    __syncthreads();

    int n0 = blockIdx.x * 128;
    int n = n0 + tid;                    // n < NP always (grid covers <= NP)
    const float* __restrict__ xb = bufPtr(inB);

    float y[NC];
#pragma unroll
    for (int c = 0; c < NC; c++) y[c] = sConst[c];

#pragma unroll 4
    for (int k = 0; k < HC; k++) {
        float xv = xb[k * NP + n];       // coalesced across warp
        const float4* wr = reinterpret_cast<const float4*>(&sLinT[k * NC]);
#pragma unroll
        for (int q = 0; q < 8; q++) {
            float4 w = wr[q];            // warp-uniform -> broadcast
            y[4 * q]     = fmaf(xv, w.x, y[4 * q]);
            y[4 * q + 1] = fmaf(xv, w.y, y[4 * q + 1]);
            y[4 * q + 2] = fmaf(xv, w.z, y[4 * q + 2]);
            y[4 * q + 3] = fmaf(xv, w.w, y[4 * q + 3]);
        }
    }
#pragma unroll
    for (int c = 0; c < NC; c++) y[c] = fmaxf(y[c], 0.f);

    // attention logits (uniform sAs/sAd reads)
    if (n < N) {
        float as[NHD] = {0.f, 0.f, 0.f, 0.f}, ad[NHD] = {0.f, 0.f, 0.f, 0.f};
#pragma unroll
        for (int hd = 0; hd < NHD; hd++) {
#pragma unroll
            for (int c = 0; c < NC; c++) {
                as[hd] = fmaf(y[c], sAs[hd * 32 + c], as[hd]);
                ad[hd] = fmaf(y[c], sAd[hd * 32 + c], ad[hd]);
            }
        }
        *reinterpret_cast<float4*>(&g_as[n * NHD]) = make_float4(as[0], as[1], as[2], as[3]);
        *reinterpret_cast<float4*>(&g_ad[n * NHD]) = make_float4(ad[0], ad[1], ad[2], ad[3]);
    }

    // y staging (stride-33 conflict-free) then coalesced row-major write
    __syncthreads();
#pragma unroll
    for (int c = 0; c < NC; c++) sY[tid * 33 + c] = y[c];
    __syncthreads();
#pragma unroll
    for (int j = 0; j < 32; j++) {
        int i = tid + j * 128;
        int ni = i >> 5, ci = i & 31;
        int nn = n0 + ni;
        if (nn < N) g_y[nn * NC + ci] = sY[ni * 33 + ci];
    }
}

// Gather: 32 nodes/block, 4 per warp; 4 edges consumed in parallel per warp.
// mode=0: transposed (channel-major) feature write + next-layer BN stats.
// mode=1: fused readout.
__global__ void __launch_bounds__(256)
k_gather(int outB, const float* __restrict__ gatW, const float* __restrict__ gatb,
         const float* __restrict__ rW, const float* __restrict__ rb,
         const int* __restrict__ batch, float* __restrict__ out,
         int l, int N, int mode) {
    __shared__ __align__(16) float sGatW[HC * 33];
    __shared__ __align__(16) float4 sW[8][32];
    __shared__ int sS[8][32];
    __shared__ __align__(16) float sOut[32][132];
    __shared__ float sRW[OUTC * HC];
    __shared__ float sGatB[HC];

    int tid = threadIdx.x;
    int wid = tid >> 5, lane = tid & 31;
    for (int m = tid; m < HC * NC; m += 256) {
        int r = m >> 5, c = m & 31;
        sGatW[r * 33 + c] = gatW[l * HC * NC + m];
    }
    if (tid < HC) sGatB[tid] = gatb[l * HC + tid];
    if (mode == 1)
        for (int m = tid; m < OUTC * HC; m += 256) sRW[m] = rW[m];
    __syncthreads();

    int hd = lane >> 3, q = lane & 7;
    int grp = lane >> 3;
    const float* __restrict__ ybase = g_y;

#pragma unroll 1
    for (int i4 = 0; i4 < 4; i4++) {
        int nl = wid * 4 + i4;
        int gw = blockIdx.x * 32 + nl;
        bool valid = (gw < N);
        int gws = valid ? gw : 0;

        int cnt = valid ? g_deg[gws] : 0;
        const int* __restrict__ lst = &g_pad[gws * CAP];
        float4 ad4 = make_float4(0.f, 0.f, 0.f, 0.f);
        float4 asSelf = make_float4(0.f, 0.f, 0.f, 0.f);
        if (valid) {
            ad4 = *reinterpret_cast<const float4*>(&g_ad[gws * NHD]);
            asSelf = *reinterpret_cast<const float4*>(&g_as[gws * NHD]);
        }
        float4 wself;
        wself.x = lrelu_exp(asSelf.x + ad4.x);
        wself.y = lrelu_exp(asSelf.y + ad4.y);
        wself.z = lrelu_exp(asSelf.z + ad4.z);
        wself.w = lrelu_exp(asSelf.w + ad4.w);

        float4 accH0 = make_float4(0.f, 0.f, 0.f, 0.f);
        float4 accH1 = make_float4(0.f, 0.f, 0.f, 0.f);
        float4 accH2 = make_float4(0.f, 0.f, 0.f, 0.f);
        float4 accH3 = make_float4(0.f, 0.f, 0.f, 0.f);
        float4 wsum4 = make_float4(0.f, 0.f, 0.f, 0.f);

        for (int base = 0; base < cnt; base += 32) {
            int c2 = min(32, cnt - base);
            int s_l = 0;
            float4 w4 = make_float4(0.f, 0.f, 0.f, 0.f);
            if (lane < c2) {
                s_l = lst[base + lane];
                const float4 as4 = *reinterpret_cast<const float4*>(&g_as[s_l * NHD]);
                w4.x = lrelu_exp(as4.x + ad4.x);
                w4.y = lrelu_exp(as4.y + ad4.y);
                w4.z = lrelu_exp(as4.z + ad4.z);
                w4.w = lrelu_exp(as4.w + ad4.w);
            }
            wsum4.x += w4.x; wsum4.y += w4.y; wsum4.z += w4.z; wsum4.w += w4.w;
            sS[wid][lane] = s_l;
            sW[wid][lane] = w4;
            __syncwarp();

            int j = grp;
            for (; j + 4 < c2; j += 8) {
                int sA = sS[wid][j], sB = sS[wid][j + 4];
                float4 weA = sW[wid][j], weB = sW[wid][j + 4];
                const float4 yA = *reinterpret_cast<const float4*>(&ybase[sA * NC + q * 4]);
                const float4 yB = *reinterpret_cast<const float4*>(&ybase[sB * NC + q * 4]);
                accH0.x = fmaf(weA.x, yA.x, accH0.x); accH0.y = fmaf(weA.x, yA.y, accH0.y);
                accH0.z = fmaf(weA.x, yA.z, accH0.z); accH0.w = fmaf(weA.x, yA.w, accH0.w);
                accH1.x = fmaf(weA.y, yA.x, accH1.x); accH1.y = fmaf(weA.y, yA.y, accH1.y);
                accH1.z = fmaf(weA.y, yA.z, accH1.z); accH1.w = fmaf(weA.y, yA.w, accH1.w);
                accH2.x = fmaf(weA.z, yA.x, accH2.x); accH2.y = fmaf(weA.z, yA.y, accH2.y);
                accH2.z = fmaf(weA.z, yA.z, accH2.z); accH2.w = fmaf(weA.z, yA.w, accH2.w);
                accH3.x = fmaf(weA.w, yA.x, accH3.x); accH3.y = fmaf(weA.w, yA.y, accH3.y);
                accH3.z = fmaf(weA.w, yA.z, accH3.z); accH3.w = fmaf(weA.w, yA.w, accH3.w);
                accH0.x = fmaf(weB.x, yB.x, accH0.x); accH0.y = fmaf(weB.x, yB.y, accH0.y);
                accH0.z = fmaf(weB.x, yB.z, accH0.z); accH0.w = fmaf(weB.x, yB.w, accH0.w);
                accH1.x = fmaf(weB.y, yB.x, accH1.x); accH1.y = fmaf(weB.y, yB.y, accH1.y);
                accH1.z = fmaf(weB.y, yB.z, accH1.z); accH1.w = fmaf(weB.y, yB.w, accH1.w);
                accH2.x = fmaf(weB.z, yB.x, accH2.x); accH2.y = fmaf(weB.z, yB.y, accH2.y);
                accH2.z = fmaf(weB.z, yB.z, accH2.z); accH2.w = fmaf(weB.z, yB.w, accH2.w);
                accH3.x = fmaf(weB.w, yB.x, accH3.x); accH3.y = fmaf(weB.w, yB.y, accH3.y);
                accH3.z = fmaf(weB.w, yB.z, accH3.z); accH3.w = fmaf(weB.w, yB.w, accH3.w);
            }
            if (j < c2) {
                int sA = sS[wid][j];
                float4 weA = sW[wid][j];
                const float4 yA = *reinterpret_cast<const float4*>(&ybase[sA * NC + q * 4]);
                accH0.x = fmaf(weA.x, yA.x, accH0.x); accH0.y = fmaf(weA.x, yA.y, accH0.y);
                accH0.z = fmaf(weA.x, yA.z, accH0.z); accH0.w = fmaf(weA.x, yA.w, accH0.w);
                accH1.x = fmaf(weA.y, yA.x, accH1.x); accH1.y = fmaf(weA.y, yA.y, accH1.y);
                accH1.z = fmaf(weA.y, yA.z, accH1.z); accH1.w = fmaf(weA.y, yA.w, accH1.w);
                accH2.x = fmaf(weA.z, yA.x, accH2.x); accH2.y = fmaf(weA.z, yA.y, accH2.y);
                accH2.z = fmaf(weA.z, yA.z, accH2.z); accH2.w = fmaf(weA.z, yA.w, accH2.w);
                accH3.x = fmaf(weA.w, yA.x, accH3.x); accH3.y = fmaf(weA.w, yA.y, accH3.y);
                accH3.z = fmaf(weA.w, yA.z, accH3.z); accH3.w = fmaf(weA.w, yA.w, accH3.w);
            }
            __syncwarp();
        }

#pragma unroll
        for (int off = 8; off <= 16; off <<= 1) {
            accH0.x += __shfl_xor_sync(0xffffffffu, accH0.x, off);
            accH0.y += __shfl_xor_sync(0xffffffffu, accH0.y, off);
            accH0.z += __shfl_xor_sync(0xffffffffu, accH0.z, off);
            accH0.w += __shfl_xor_sync(0xffffffffu, accH0.w, off);
            accH1.x += __shfl_xor_sync(0xffffffffu, accH1.x, off);
            accH1.y += __shfl_xor_sync(0xffffffffu, accH1.y, off);
            accH1.z += __shfl_xor_sync(0xffffffffu, accH1.z, off);
            accH1.w += __shfl_xor_sync(0xffffffffu, accH1.w, off);
            accH2.x += __shfl_xor_sync(0xffffffffu, accH2.x, off);
            accH2.y += __shfl_xor_sync(0xffffffffu, accH2.y, off);
            accH2.z += __shfl_xor_sync(0xffffffffu, accH2.z, off);
            accH2.w += __shfl_xor_sync(0xffffffffu, accH2.w, off);
            accH3.x += __shfl_xor_sync(0xffffffffu, accH3.x, off);
            accH3.y += __shfl_xor_sync(0xffffffffu, accH3.y, off);
            accH3.z += __shfl_xor_sync(0xffffffffu, accH3.z, off);
            accH3.w += __shfl_xor_sync(0xffffffffu, accH3.w, off);
        }
        float4 acc = (hd == 0) ? accH0 : (hd == 1) ? accH1 : (hd == 2) ? accH2 : accH3;

#pragma unroll
        for (int off = 16; off; off >>= 1) {
            wsum4.x += __shfl_xor_sync(0xffffffffu, wsum4.x, off);
            wsum4.y += __shfl_xor_sync(0xffffffffu, wsum4.y, off);
            wsum4.z += __shfl_xor_sync(0xffffffffu, wsum4.z, off);
            wsum4.w += __shfl_xor_sync(0xffffffffu, wsum4.w, off);
        }
        wsum4.x += wself.x; wsum4.y += wself.y; wsum4.z += wself.z; wsum4.w += wself.w;
        float wsh = (hd == 0) ? wself.x : (hd == 1) ? wself.y : (hd == 2) ? wself.z : wself.w;
        const float4 ys = *reinterpret_cast<const float4*>(&ybase[gws * NC + q * 4]);
        acc.x = fmaf(wsh, ys.x, acc.x); acc.y = fmaf(wsh, ys.y, acc.y);
        acc.z = fmaf(wsh, ys.z, acc.z); acc.w = fmaf(wsh, ys.w, acc.w);
        float wsumh = (hd == 0) ? wsum4.x : (hd == 1) ? wsum4.y : (hd == 2) ? wsum4.z : wsum4.w;
        float inv = 1.f / (wsumh + 1e-16f);
        acc.x *= inv; acc.y *= inv; acc.z *= inv; acc.w *= inv;

        *reinterpret_cast<float4*>(&sOut[nl][lane * 4]) = acc;
        __syncwarp();

        float a[4];
#pragma unroll
        for (int i = 0; i < 4; i++) {
            int o = lane + 32 * i;
            float v = sGatB[o];
            const float* aggh = &sOut[nl][i * 32];
            const float* wrow = &sGatW[o * 33];
#pragma unroll
            for (int c = 0; c < 32; c++) v = fmaf(wrow[c], aggh[c], v);
            a[i] = valid ? v : 0.f;
        }
        __syncwarp();
#pragma unroll
        for (int i = 0; i < 4; i++) sOut[nl][lane + 32 * i] = a[i];

        if (mode == 1 && valid) {
            int g = batch[gw];
#pragma unroll
            for (int o = 0; o < OUTC; o++) {
                float pdot = 0.f;
#pragma unroll
                for (int i = 0; i < 4; i++)
                    pdot = fmaf(a[i], sRW[o * HC + lane + 32 * i], pdot);
#pragma unroll
                for (int off = 16; off; off >>= 1)
                    pdot += __shfl_xor_sync(0xffffffffu, pdot, off);
                if (lane == o) atomicAdd(&out[g * OUTC + o], pdot + __ldg(&rb[o]));
            }
        }
    }

    if (mode == 0) {
        __syncthreads();
        // next-layer BN stats: tree reduce over the block's 32 node rows
        if (tid < HC) {
            float s = 0.f, s2 = 0.f;
#pragma unroll
            for (int w = 0; w < 32; w++) {
                float v = sOut[w][tid];
                s += v; s2 += v * v;
            }
            atomicAdd(&g_sumL[l + 1][tid], s);
            atomicAdd(&g_sqL[l + 1][tid], s2);
        }
        // transposed (channel-major) feature write
        float* ob = bufPtr(outB);
        int node = tid & 31;
        int gw2 = blockIdx.x * 32 + node;
        if (gw2 < N) {
            int cb = tid >> 5;               // 0..7
#pragma unroll
            for (int p = 0; p < 16; p++) {
                int cc = cb * 16 + p;
                ob[cc * NP + gw2] = sOut[node][cc];
            }
        }
    }
}

// ---------------- launch ----------------
extern "C" void kernel_launch(void* const* d_in, const int* in_sizes, int n_in,
                              void* d_out, int out_size) {
    const int*   xidx  = (const int*)d_in[0];
    const int*   ei    = (const int*)d_in[1];
    const int*   batch = (const int*)d_in[2];
    const float* embed = (const float*)d_in[3];
    const float* bng   = (const float*)d_in[4];
    const float* bnb   = (const float*)d_in[5];
    const float* linW  = (const float*)d_in[6];
    const float* linb  = (const float*)d_in[7];
    const float* gatW  = (const float*)d_in[8];
    const float* attS  = (const float*)d_in[9];
    const float* attD  = (const float*)d_in[10];
    const float* gatb  = (const float*)d_in[11];
    const float* rW    = (const float*)d_in[12];
    const float* rb    = (const float*)d_in[13];
    float* out = (float*)d_out;

    int N = in_sizes[0];
    int E = in_sizes[1] / 2;
    int nA = (N + 63) / 64;
    int nB = (E + 255) / 256;

    k_init<<<(N + 255) / 256, 256>>>(out, out_size, N);
    k_embed_scatter<<<nA + nB, 256>>>(xidx, embed, ei, N, E, nA);

    for (int l = 0; l < NL; l++) {
        int inB = l & 1;
        int outB = inB ^ 1;
        int mode = (l == NL - 1) ? 1 : 0;
        k_prep<<<1, 128>>>(l, linW, linb, gatW, attS, attD, bng, bnb, N);
        k_node<<<(N + 127) / 128, 128>>>(inB, N);
        k_gather<<<(N + 31) / 32, 256>>>(outB, gatW, gatb, rW, rb, batch, out, l, N, mode);
    }
}